// round 1
// baseline (speedup 1.0000x reference)
#include <cuda_runtime.h>
#include <cstdint>

// Problem constants
#define B_  4
#define T_  2048
#define C_  1024
#define H_  16
#define D_  64
#define M_  (B_ * T_)      // 8192 rows
#define W3_ (3 * C_)       // 3072

// Scratch (allocation-free rule: __device__ globals)
__device__ float g_qkv[(size_t)M_ * W3_];  // [8192, 3072] fp32
__device__ float g_y[(size_t)M_ * C_];     // [8192, 1024] fp32

// ---------------------------------------------------------------------------
// Tiled fp32 GEMM with bias: Out[M,N] = A[M,K] @ W[K,N] + bias[N]
// BM=BN=64, BK=16, 256 threads, 4x4 per thread.
// ---------------------------------------------------------------------------
__global__ void __launch_bounds__(256) gemm_bias_kernel(
    const float* __restrict__ A, const float* __restrict__ W,
    const float* __restrict__ bias, float* __restrict__ Out,
    int M, int K, int N)
{
    __shared__ float As[16][68];   // k-major: As[k][row], padded
    __shared__ float Bs[16][68];   // Bs[k][col], padded

    const int tid = threadIdx.x;
    const int tx = tid & 15;
    const int ty = tid >> 4;
    const int bm = blockIdx.y * 64;
    const int bn = blockIdx.x * 64;

    const int arow = tid >> 2;          // 0..63
    const int ak   = (tid & 3) << 2;    // 0,4,8,12
    const int brow = tid >> 4;          // 0..15
    const int bcol = (tid & 15) << 2;   // 0..60

    const float* Ap = A + (size_t)(bm + arow) * K + ak;
    const float* Wp = W + (size_t)brow * N + bn + bcol;

    float acc[4][4] = {};

    for (int k0 = 0; k0 < K; k0 += 16) {
        float4 av = *(const float4*)(Ap + k0);
        float4 bv = *(const float4*)(Wp + (size_t)k0 * N);

        As[ak + 0][arow] = av.x;
        As[ak + 1][arow] = av.y;
        As[ak + 2][arow] = av.z;
        As[ak + 3][arow] = av.w;
        *(float4*)&Bs[brow][bcol] = bv;
        __syncthreads();

        #pragma unroll
        for (int kk = 0; kk < 16; kk++) {
            float4 a4 = *(const float4*)&As[kk][ty << 2];
            float4 b4 = *(const float4*)&Bs[kk][tx << 2];
            float a[4] = {a4.x, a4.y, a4.z, a4.w};
            float b[4] = {b4.x, b4.y, b4.z, b4.w};
            #pragma unroll
            for (int i = 0; i < 4; i++)
                #pragma unroll
                for (int j = 0; j < 4; j++)
                    acc[i][j] += a[i] * b[j];
        }
        __syncthreads();
    }

    float4 bb = *(const float4*)&bias[bn + (tx << 2)];
    float bvec[4] = {bb.x, bb.y, bb.z, bb.w};
    #pragma unroll
    for (int i = 0; i < 4; i++) {
        float4 o;
        o.x = acc[i][0] + bvec[0];
        o.y = acc[i][1] + bvec[1];
        o.z = acc[i][2] + bvec[2];
        o.w = acc[i][3] + bvec[3];
        *(float4*)&Out[(size_t)(bm + (ty << 2) + i) * N + bn + (tx << 2)] = o;
    }
}

// ---------------------------------------------------------------------------
// Causal flash attention, fp32.
// Grid: (T/64, H, B). 256 threads. Q tile 64 rows, K tile 64 rows, D=64.
// Online softmax (m, l per row). Score scale = sqrt(D) = 8 (faithful bug).
// ---------------------------------------------------------------------------
#define QS_STRIDE 68
#define SS_STRIDE 68
// smem floats: Qs 64*68 + Ks 64*68 + Vs 64*64 + Ss 64*68 + 3*64
#define ATTN_SMEM_FLOATS (64*68 + 64*68 + 64*64 + 64*68 + 3*64)
#define ATTN_SMEM_BYTES  (ATTN_SMEM_FLOATS * 4)

__global__ void __launch_bounds__(256) attn_kernel(
    const float* __restrict__ qkv, float* __restrict__ y)
{
    extern __shared__ float sm[];
    float* Qs   = sm;                      // [64][68], d-major: Qs[d][row]
    float* Ks   = Qs + 64 * QS_STRIDE;     // [64][68], d-major: Ks[d][col]
    float* Vs   = Ks + 64 * QS_STRIDE;     // [64][64], natural: Vs[k][d]
    float* Ss   = Vs + 64 * 64;            // [64][68]
    float* arow = Ss + 64 * SS_STRIDE;     // [64] per-row rescale alpha
    float* mrow = arow + 64;               // [64] running max
    float* lrow = mrow + 64;               // [64] running sum

    const int tid = threadIdx.x;
    const int tx = tid & 15;
    const int ty = tid >> 4;
    const int qi = blockIdx.x;
    const int h  = blockIdx.y;
    const int b  = blockIdx.z;

    const float* qbase = qkv + (size_t)b * T_ * W3_ + h * D_;
    const float* kbase = qbase + C_;
    const float* vbase = qbase + 2 * C_;

    // Load Q tile, transposed to d-major
    #pragma unroll
    for (int l = 0; l < 4; l++) {
        int idx = tid + 256 * l;
        int r   = idx >> 4;            // 0..63
        int d4  = (idx & 15) << 2;     // 0..60
        float4 v = *(const float4*)(qbase + (size_t)(qi * 64 + r) * W3_ + d4);
        Qs[(d4 + 0) * QS_STRIDE + r] = v.x;
        Qs[(d4 + 1) * QS_STRIDE + r] = v.y;
        Qs[(d4 + 2) * QS_STRIDE + r] = v.z;
        Qs[(d4 + 3) * QS_STRIDE + r] = v.w;
    }
    if (tid < 64) { mrow[tid] = -1e30f; lrow[tid] = 0.0f; }

    float o[4][4] = {};

    for (int kj = 0; kj <= qi; kj++) {
        __syncthreads();  // previous PV done (Vs/Ss free); Qs/init visible
        // Load K (transposed) and V (natural) tiles
        #pragma unroll
        for (int l = 0; l < 4; l++) {
            int idx = tid + 256 * l;
            int r   = idx >> 4;
            int d4  = (idx & 15) << 2;
            float4 kv = *(const float4*)(kbase + (size_t)(kj * 64 + r) * W3_ + d4);
            Ks[(d4 + 0) * QS_STRIDE + r] = kv.x;
            Ks[(d4 + 1) * QS_STRIDE + r] = kv.y;
            Ks[(d4 + 2) * QS_STRIDE + r] = kv.z;
            Ks[(d4 + 3) * QS_STRIDE + r] = kv.w;
            float4 vv = *(const float4*)(vbase + (size_t)(kj * 64 + r) * W3_ + d4);
            *(float4*)&Vs[r * 64 + d4] = vv;
        }
        __syncthreads();

        // S = (Q K^T) * 8, per-thread 4x4 tile
        float s[4][4] = {};
        #pragma unroll 8
        for (int d = 0; d < 64; d++) {
            float4 a4 = *(const float4*)&Qs[d * QS_STRIDE + (ty << 2)];
            float4 b4 = *(const float4*)&Ks[d * QS_STRIDE + (tx << 2)];
            float a[4] = {a4.x, a4.y, a4.z, a4.w};
            float bb[4] = {b4.x, b4.y, b4.z, b4.w};
            #pragma unroll
            for (int i = 0; i < 4; i++)
                #pragma unroll
                for (int j = 0; j < 4; j++)
                    s[i][j] += a[i] * bb[j];
        }

        const bool diag = (kj == qi);
        #pragma unroll
        for (int i = 0; i < 4; i++) {
            #pragma unroll
            for (int j = 0; j < 4; j++) {
                float val = s[i][j] * 8.0f;
                if (diag && ((tx << 2) + j > (ty << 2) + i)) val = -1e30f;
                Ss[((ty << 2) + i) * SS_STRIDE + (tx << 2) + j] = val;
            }
        }
        __syncthreads();

        // Online softmax: one thread per row
        if (tid < 64) {
            const int r = tid;
            float mold = mrow[r];
            float mx = mold;
            #pragma unroll 8
            for (int j = 0; j < 64; j++)
                mx = fmaxf(mx, Ss[r * SS_STRIDE + j]);
            float al = __expf(mold - mx);
            float sum = 0.0f;
            #pragma unroll 8
            for (int j = 0; j < 64; j++) {
                float p = __expf(Ss[r * SS_STRIDE + j] - mx);
                Ss[r * SS_STRIDE + j] = p;
                sum += p;
            }
            lrow[r] = lrow[r] * al + sum;
            mrow[r] = mx;
            arow[r] = al;
        }
        __syncthreads();

        // Rescale O by alpha, then O += P @ V
        #pragma unroll
        for (int i = 0; i < 4; i++) {
            float al = arow[(ty << 2) + i];
            #pragma unroll
            for (int j = 0; j < 4; j++) o[i][j] *= al;
        }

        #pragma unroll 4
        for (int k4 = 0; k4 < 16; k4++) {
            float pv[4][4];
            #pragma unroll
            for (int i = 0; i < 4; i++) {
                float4 p = *(const float4*)&Ss[((ty << 2) + i) * SS_STRIDE + (k4 << 2)];
                pv[i][0] = p.x; pv[i][1] = p.y; pv[i][2] = p.z; pv[i][3] = p.w;
            }
            #pragma unroll
            for (int kk = 0; kk < 4; kk++) {
                float4 v4 = *(const float4*)&Vs[((k4 << 2) + kk) * 64 + (tx << 2)];
                #pragma unroll
                for (int i = 0; i < 4; i++) {
                    o[i][0] += pv[i][kk] * v4.x;
                    o[i][1] += pv[i][kk] * v4.y;
                    o[i][2] += pv[i][kk] * v4.z;
                    o[i][3] += pv[i][kk] * v4.w;
                }
            }
        }
    }

    // Epilogue: normalize and write y[b, t, h*D + d]  (i.e. [8192, 1024])
    #pragma unroll
    for (int i = 0; i < 4; i++) {
        int tq = qi * 64 + (ty << 2) + i;
        float inv = 1.0f / lrow[(ty << 2) + i];
        float4 ov;
        ov.x = o[i][0] * inv;
        ov.y = o[i][1] * inv;
        ov.z = o[i][2] * inv;
        ov.w = o[i][3] * inv;
        *(float4*)&y[(size_t)(b * T_ + tq) * C_ + h * D_ + (tx << 2)] = ov;
    }
}

// ---------------------------------------------------------------------------
// Launch
// ---------------------------------------------------------------------------
extern "C" void kernel_launch(void* const* d_in, const int* in_sizes, int n_in,
                              void* d_out, int out_size)
{
    const float* x      = (const float*)d_in[0];
    const float* w_attn = (const float*)d_in[1];
    const float* b_attn = (const float*)d_in[2];
    const float* w_proj = (const float*)d_in[3];
    const float* b_proj = (const float*)d_in[4];
    float* out = (float*)d_out;

    float* qkv = nullptr;
    float* y   = nullptr;
    cudaGetSymbolAddress((void**)&qkv, g_qkv);
    cudaGetSymbolAddress((void**)&y, g_y);

    cudaFuncSetAttribute(attn_kernel,
                         cudaFuncAttributeMaxDynamicSharedMemorySize,
                         ATTN_SMEM_BYTES);

    dim3 blk(256);

    // qkv = x @ w_attn + b_attn   : [8192,1024] @ [1024,3072]
    gemm_bias_kernel<<<dim3(W3_ / 64, M_ / 64), blk>>>(x, w_attn, b_attn, qkv,
                                                       M_, C_, W3_);

    // y = causal_attention(q, k, v)
    attn_kernel<<<dim3(T_ / 64, H_, B_), blk, ATTN_SMEM_BYTES>>>(qkv, y);

    // out = y @ w_proj + b_proj  : [8192,1024] @ [1024,1024]
    gemm_bias_kernel<<<dim3(C_ / 64, M_ / 64), blk>>>(y, w_proj, b_proj, out,
                                                      M_, C_, C_);
}

// round 4
// speedup vs baseline: 1.6241x; 1.6241x over previous
#include <cuda_runtime.h>
#include <cuda_fp16.h>
#include <cstdint>

// Problem constants
#define B_  4
#define T_  2048
#define C_  1024
#define H_  16
#define D_  64
#define M_  (B_ * T_)      // 8192 rows
#define W3_ (3 * C_)       // 3072

// Scratch (allocation-free rule: __device__ globals)
__device__ float g_qkv[(size_t)M_ * W3_];  // [8192, 3072] fp32
__device__ float g_y[(size_t)M_ * C_];     // [8192, 1024] fp32

// ---------------------------------------------------------------------------
// fp16 m16n8k16 MMA with fp32 accumulate (legacy path, valid on compute_103)
// ---------------------------------------------------------------------------
__device__ __forceinline__ void mma_f16(float* acc, const uint32_t* a,
                                        const uint32_t* b) {
    asm volatile(
        "mma.sync.aligned.m16n8k16.row.col.f32.f16.f16.f32 "
        "{%0,%1,%2,%3}, {%4,%5,%6,%7}, {%8,%9}, {%0,%1,%2,%3};"
        : "+f"(acc[0]), "+f"(acc[1]), "+f"(acc[2]), "+f"(acc[3])
        : "r"(a[0]), "r"(a[1]), "r"(a[2]), "r"(a[3]),
          "r"(b[0]), "r"(b[1]));
}

__device__ __forceinline__ void split2(float x, float y, __half2& hi, __half2& lo) {
    hi = __float22half2_rn(make_float2(x, y));
    float2 h = __half22float2(hi);
    lo = __float22half2_rn(make_float2(x - h.x, y - h.y));
}

// ---------------------------------------------------------------------------
// Split-fp16 tensor GEMM with bias: Out[M,N] = A[M,K] @ W[K,N] + bias[N]
// 128x128 CTA tile, BK=32, 256 threads (8 warps as 4Mx2N), warp tile 32x64.
// Each operand split hi+lo fp16; 3 MMA terms; fp32 accumulators.
// SMEM per stage: A_hi/A_lo [128][40]h + B_hi/B_lo [128 n][40]h = 40 KB.
// Double-buffered: 80 KB -> 2 CTAs/SM.
// ---------------------------------------------------------------------------
#define APITCH 40
#define A_TILE_H (128 * APITCH)          // 5120 halves per tile
#define STAGE_H  (4 * A_TILE_H)          // Ahi, Alo, Bhi, Blo
#define GEMM_SMEM_BYTES (2 * STAGE_H * 2)  // 81920 bytes

__global__ void __launch_bounds__(256, 2) gemm_split16_kernel(
    const float* __restrict__ A, const float* __restrict__ W,
    const float* __restrict__ bias, float* __restrict__ Out,
    int M, int K, int N)
{
    extern __shared__ __half smh[];

    const int tid  = threadIdx.x;
    const int w    = tid >> 5;
    const int lane = tid & 31;
    const int g    = lane >> 2;       // 0..7
    const int tig  = lane & 3;        // 0..3
    const int wm   = (w & 3) * 32;
    const int wn   = (w >> 2) * 64;

    const int bm = blockIdx.y * 128;
    const int bn = blockIdx.x * 128;

    // staging indices
    const int am  = tid >> 3;         // A row (0..31, +32/l)
    const int akq = tid & 7;          // A k-quad
    const int bn0 = tid & 31;         // B n (0..31, +32/l)
    const int bkq = tid >> 5;         // B k-quad (0..7)

    float acc[2][8][4] = {};
    float4 areg[4];
    float  breg[4][4];

    const int nchunk = K >> 5;

    // ---- prologue: global load chunk 0 ----
    #pragma unroll
    for (int l = 0; l < 4; l++) {
        areg[l] = *(const float4*)(A + (size_t)(bm + am + 32 * l) * K + (akq << 2));
        const float* wp = W + (size_t)(bkq << 2) * N + bn + bn0 + 32 * l;
        breg[l][0] = wp[0];
        breg[l][1] = wp[N];
        breg[l][2] = wp[2 * (size_t)N];
        breg[l][3] = wp[3 * (size_t)N];
    }
    {
        __half* Ahi = smh;
        __half* Alo = smh + A_TILE_H;
        __half* Bhi = smh + 2 * A_TILE_H;
        __half* Blo = smh + 3 * A_TILE_H;
        #pragma unroll
        for (int l = 0; l < 4; l++) {
            int m = am + 32 * l;
            __half2 h01, l01, h23, l23;
            split2(areg[l].x, areg[l].y, h01, l01);
            split2(areg[l].z, areg[l].w, h23, l23);
            *(__half2*)&Ahi[m * APITCH + (akq << 2)]     = h01;
            *(__half2*)&Ahi[m * APITCH + (akq << 2) + 2] = h23;
            *(__half2*)&Alo[m * APITCH + (akq << 2)]     = l01;
            *(__half2*)&Alo[m * APITCH + (akq << 2) + 2] = l23;
            int n = bn0 + 32 * l;
            split2(breg[l][0], breg[l][1], h01, l01);
            split2(breg[l][2], breg[l][3], h23, l23);
            *(__half2*)&Bhi[n * APITCH + (bkq << 2)]     = h01;
            *(__half2*)&Bhi[n * APITCH + (bkq << 2) + 2] = h23;
            *(__half2*)&Blo[n * APITCH + (bkq << 2)]     = l01;
            *(__half2*)&Blo[n * APITCH + (bkq << 2) + 2] = l23;
        }
    }
    __syncthreads();

    for (int c = 0; c < nchunk; c++) {
        // prefetch next chunk into registers
        if (c + 1 < nchunk) {
            const int k0 = (c + 1) << 5;
            #pragma unroll
            for (int l = 0; l < 4; l++) {
                areg[l] = *(const float4*)(A + (size_t)(bm + am + 32 * l) * K + k0 + (akq << 2));
                const float* wp = W + (size_t)(k0 + (bkq << 2)) * N + bn + bn0 + 32 * l;
                breg[l][0] = wp[0];
                breg[l][1] = wp[N];
                breg[l][2] = wp[2 * (size_t)N];
                breg[l][3] = wp[3 * (size_t)N];
            }
        }

        // compute on current buffer
        const __half* Ahi = smh + (c & 1) * STAGE_H;
        const __half* Alo = Ahi + A_TILE_H;
        const __half* Bhi = Ahi + 2 * A_TILE_H;
        const __half* Blo = Ahi + 3 * A_TILE_H;

        #pragma unroll
        for (int ks = 0; ks < 2; ks++) {
            const int ck = (ks << 4) + (tig << 1);
            uint32_t ah[2][4], al[2][4];
            #pragma unroll
            for (int ti = 0; ti < 2; ti++) {
                const int r0 = wm + (ti << 4) + g;
                ah[ti][0] = *(const uint32_t*)&Ahi[r0 * APITCH + ck];
                ah[ti][1] = *(const uint32_t*)&Ahi[(r0 + 8) * APITCH + ck];
                ah[ti][2] = *(const uint32_t*)&Ahi[r0 * APITCH + ck + 8];
                ah[ti][3] = *(const uint32_t*)&Ahi[(r0 + 8) * APITCH + ck + 8];
                al[ti][0] = *(const uint32_t*)&Alo[r0 * APITCH + ck];
                al[ti][1] = *(const uint32_t*)&Alo[(r0 + 8) * APITCH + ck];
                al[ti][2] = *(const uint32_t*)&Alo[r0 * APITCH + ck + 8];
                al[ti][3] = *(const uint32_t*)&Alo[(r0 + 8) * APITCH + ck + 8];
            }
            #pragma unroll
            for (int j = 0; j < 8; j++) {
                const int col = wn + (j << 3) + g;
                uint32_t bh[2], bl[2];
                bh[0] = *(const uint32_t*)&Bhi[col * APITCH + ck];
                bh[1] = *(const uint32_t*)&Bhi[col * APITCH + ck + 8];
                bl[0] = *(const uint32_t*)&Blo[col * APITCH + ck];
                bl[1] = *(const uint32_t*)&Blo[col * APITCH + ck + 8];
                #pragma unroll
                for (int ti = 0; ti < 2; ti++) {
                    mma_f16(acc[ti][j], ah[ti], bh);
                    mma_f16(acc[ti][j], ah[ti], bl);
                    mma_f16(acc[ti][j], al[ti], bh);
                }
            }
        }

        // store next chunk to the other buffer
        if (c + 1 < nchunk) {
            __half* Ahin = smh + ((c + 1) & 1) * STAGE_H;
            __half* Alon = Ahin + A_TILE_H;
            __half* Bhin = Ahin + 2 * A_TILE_H;
            __half* Blon = Ahin + 3 * A_TILE_H;
            #pragma unroll
            for (int l = 0; l < 4; l++) {
                int m = am + 32 * l;
                __half2 h01, l01, h23, l23;
                split2(areg[l].x, areg[l].y, h01, l01);
                split2(areg[l].z, areg[l].w, h23, l23);
                *(__half2*)&Ahin[m * APITCH + (akq << 2)]     = h01;
                *(__half2*)&Ahin[m * APITCH + (akq << 2) + 2] = h23;
                *(__half2*)&Alon[m * APITCH + (akq << 2)]     = l01;
                *(__half2*)&Alon[m * APITCH + (akq << 2) + 2] = l23;
                int n = bn0 + 32 * l;
                split2(breg[l][0], breg[l][1], h01, l01);
                split2(breg[l][2], breg[l][3], h23, l23);
                *(__half2*)&Bhin[n * APITCH + (bkq << 2)]     = h01;
                *(__half2*)&Bhin[n * APITCH + (bkq << 2) + 2] = h23;
                *(__half2*)&Blon[n * APITCH + (bkq << 2)]     = l01;
                *(__half2*)&Blon[n * APITCH + (bkq << 2) + 2] = l23;
            }
        }
        __syncthreads();
    }

    // ---- epilogue: bias + store ----
    #pragma unroll
    for (int j = 0; j < 8; j++) {
        const int col = bn + wn + (j << 3) + (tig << 1);
        const float2 bb = *(const float2*)(bias + col);
        #pragma unroll
        for (int ti = 0; ti < 2; ti++) {
            const int row = bm + wm + (ti << 4) + g;
            float2 o0, o1;
            o0.x = acc[ti][j][0] + bb.x;
            o0.y = acc[ti][j][1] + bb.y;
            o1.x = acc[ti][j][2] + bb.x;
            o1.y = acc[ti][j][3] + bb.y;
            *(float2*)(Out + (size_t)row * N + col)       = o0;
            *(float2*)(Out + (size_t)(row + 8) * N + col) = o1;
        }
    }
}

// ---------------------------------------------------------------------------
// Causal flash attention, fp32 (unchanged — passing baseline).
// ---------------------------------------------------------------------------
#define QS_STRIDE 68
#define SS_STRIDE 68
#define ATTN_SMEM_FLOATS (64*68 + 64*68 + 64*64 + 64*68 + 3*64)
#define ATTN_SMEM_BYTES  (ATTN_SMEM_FLOATS * 4)

__global__ void __launch_bounds__(256) attn_kernel(
    const float* __restrict__ qkv, float* __restrict__ y)
{
    extern __shared__ float sm[];
    float* Qs   = sm;
    float* Ks   = Qs + 64 * QS_STRIDE;
    float* Vs   = Ks + 64 * QS_STRIDE;
    float* Ss   = Vs + 64 * 64;
    float* arow = Ss + 64 * SS_STRIDE;
    float* mrow = arow + 64;
    float* lrow = mrow + 64;

    const int tid = threadIdx.x;
    const int tx = tid & 15;
    const int ty = tid >> 4;
    const int qi = blockIdx.x;
    const int h  = blockIdx.y;
    const int b  = blockIdx.z;

    const float* qbase = qkv + (size_t)b * T_ * W3_ + h * D_;
    const float* kbase = qbase + C_;
    const float* vbase = qbase + 2 * C_;

    #pragma unroll
    for (int l = 0; l < 4; l++) {
        int idx = tid + 256 * l;
        int r   = idx >> 4;
        int d4  = (idx & 15) << 2;
        float4 v = *(const float4*)(qbase + (size_t)(qi * 64 + r) * W3_ + d4);
        Qs[(d4 + 0) * QS_STRIDE + r] = v.x;
        Qs[(d4 + 1) * QS_STRIDE + r] = v.y;
        Qs[(d4 + 2) * QS_STRIDE + r] = v.z;
        Qs[(d4 + 3) * QS_STRIDE + r] = v.w;
    }
    if (tid < 64) { mrow[tid] = -1e30f; lrow[tid] = 0.0f; }

    float o[4][4] = {};

    for (int kj = 0; kj <= qi; kj++) {
        __syncthreads();
        #pragma unroll
        for (int l = 0; l < 4; l++) {
            int idx = tid + 256 * l;
            int r   = idx >> 4;
            int d4  = (idx & 15) << 2;
            float4 kv = *(const float4*)(kbase + (size_t)(kj * 64 + r) * W3_ + d4);
            Ks[(d4 + 0) * QS_STRIDE + r] = kv.x;
            Ks[(d4 + 1) * QS_STRIDE + r] = kv.y;
            Ks[(d4 + 2) * QS_STRIDE + r] = kv.z;
            Ks[(d4 + 3) * QS_STRIDE + r] = kv.w;
            float4 vv = *(const float4*)(vbase + (size_t)(kj * 64 + r) * W3_ + d4);
            *(float4*)&Vs[r * 64 + d4] = vv;
        }
        __syncthreads();

        float s[4][4] = {};
        #pragma unroll 8
        for (int d = 0; d < 64; d++) {
            float4 a4 = *(const float4*)&Qs[d * QS_STRIDE + (ty << 2)];
            float4 b4 = *(const float4*)&Ks[d * QS_STRIDE + (tx << 2)];
            float a[4] = {a4.x, a4.y, a4.z, a4.w};
            float bb[4] = {b4.x, b4.y, b4.z, b4.w};
            #pragma unroll
            for (int i = 0; i < 4; i++)
                #pragma unroll
                for (int j = 0; j < 4; j++)
                    s[i][j] += a[i] * bb[j];
        }

        const bool diag = (kj == qi);
        #pragma unroll
        for (int i = 0; i < 4; i++) {
            #pragma unroll
            for (int j = 0; j < 4; j++) {
                float val = s[i][j] * 8.0f;
                if (diag && ((tx << 2) + j > (ty << 2) + i)) val = -1e30f;
                Ss[((ty << 2) + i) * SS_STRIDE + (tx << 2) + j] = val;
            }
        }
        __syncthreads();

        if (tid < 64) {
            const int r = tid;
            float mold = mrow[r];
            float mx = mold;
            #pragma unroll 8
            for (int j = 0; j < 64; j++)
                mx = fmaxf(mx, Ss[r * SS_STRIDE + j]);
            float al = __expf(mold - mx);
            float sum = 0.0f;
            #pragma unroll 8
            for (int j = 0; j < 64; j++) {
                float p = __expf(Ss[r * SS_STRIDE + j] - mx);
                Ss[r * SS_STRIDE + j] = p;
                sum += p;
            }
            lrow[r] = lrow[r] * al + sum;
            mrow[r] = mx;
            arow[r] = al;
        }
        __syncthreads();

        #pragma unroll
        for (int i = 0; i < 4; i++) {
            float al = arow[(ty << 2) + i];
            #pragma unroll
            for (int j = 0; j < 4; j++) o[i][j] *= al;
        }

        #pragma unroll 4
        for (int k4 = 0; k4 < 16; k4++) {
            float pv[4][4];
            #pragma unroll
            for (int i = 0; i < 4; i++) {
                float4 p = *(const float4*)&Ss[((ty << 2) + i) * SS_STRIDE + (k4 << 2)];
                pv[i][0] = p.x; pv[i][1] = p.y; pv[i][2] = p.z; pv[i][3] = p.w;
            }
            #pragma unroll
            for (int kk = 0; kk < 4; kk++) {
                float4 v4 = *(const float4*)&Vs[((k4 << 2) + kk) * 64 + (tx << 2)];
                #pragma unroll
                for (int i = 0; i < 4; i++) {
                    o[i][0] += pv[i][kk] * v4.x;
                    o[i][1] += pv[i][kk] * v4.y;
                    o[i][2] += pv[i][kk] * v4.z;
                    o[i][3] += pv[i][kk] * v4.w;
                }
            }
        }
    }

    #pragma unroll
    for (int i = 0; i < 4; i++) {
        int tq = qi * 64 + (ty << 2) + i;
        float inv = 1.0f / lrow[(ty << 2) + i];
        float4 ov;
        ov.x = o[i][0] * inv;
        ov.y = o[i][1] * inv;
        ov.z = o[i][2] * inv;
        ov.w = o[i][3] * inv;
        *(float4*)&y[(size_t)(b * T_ + tq) * C_ + h * D_ + (tx << 2)] = ov;
    }
}

// ---------------------------------------------------------------------------
// Launch
// ---------------------------------------------------------------------------
extern "C" void kernel_launch(void* const* d_in, const int* in_sizes, int n_in,
                              void* d_out, int out_size)
{
    const float* x      = (const float*)d_in[0];
    const float* w_attn = (const float*)d_in[1];
    const float* b_attn = (const float*)d_in[2];
    const float* w_proj = (const float*)d_in[3];
    const float* b_proj = (const float*)d_in[4];
    float* out = (float*)d_out;

    float* qkv = nullptr;
    float* y   = nullptr;
    cudaGetSymbolAddress((void**)&qkv, g_qkv);
    cudaGetSymbolAddress((void**)&y, g_y);

    cudaFuncSetAttribute(gemm_split16_kernel,
                         cudaFuncAttributeMaxDynamicSharedMemorySize,
                         GEMM_SMEM_BYTES);
    cudaFuncSetAttribute(attn_kernel,
                         cudaFuncAttributeMaxDynamicSharedMemorySize,
                         ATTN_SMEM_BYTES);

    // qkv = x @ w_attn + b_attn : [8192,1024]@[1024,3072]
    gemm_split16_kernel<<<dim3(W3_ / 128, M_ / 128), 256, GEMM_SMEM_BYTES>>>(
        x, w_attn, b_attn, qkv, M_, C_, W3_);

    // y = causal_attention(q, k, v)
    attn_kernel<<<dim3(T_ / 64, H_, B_), 256, ATTN_SMEM_BYTES>>>(qkv, y);

    // out = y @ w_proj + b_proj : [8192,1024]@[1024,1024]
    gemm_split16_kernel<<<dim3(C_ / 128, M_ / 128), 256, GEMM_SMEM_BYTES>>>(
        y, w_proj, b_proj, out, M_, C_, C_);
}

// round 5
// speedup vs baseline: 2.3221x; 1.4298x over previous
#include <cuda_runtime.h>
#include <cuda_fp16.h>
#include <cstdint>

// Problem constants
#define B_  4
#define T_  2048
#define C_  1024
#define H_  16
#define D_  64
#define M_  (B_ * T_)      // 8192 rows
#define W3_ (3 * C_)       // 3072

// Scratch (allocation-free rule: __device__ globals)
__device__ float g_qkv[(size_t)M_ * W3_];  // [8192, 3072] fp32
__device__ float g_y[(size_t)M_ * C_];     // [8192, 1024] fp32

// ---------------------------------------------------------------------------
// fp16 m16n8k16 MMA with fp32 accumulate (legacy path, valid on compute_103)
// ---------------------------------------------------------------------------
__device__ __forceinline__ void mma_f16(float* acc, const uint32_t* a,
                                        const uint32_t* b) {
    asm volatile(
        "mma.sync.aligned.m16n8k16.row.col.f32.f16.f16.f32 "
        "{%0,%1,%2,%3}, {%4,%5,%6,%7}, {%8,%9}, {%0,%1,%2,%3};"
        : "+f"(acc[0]), "+f"(acc[1]), "+f"(acc[2]), "+f"(acc[3])
        : "r"(a[0]), "r"(a[1]), "r"(a[2]), "r"(a[3]),
          "r"(b[0]), "r"(b[1]));
}

__device__ __forceinline__ void split2(float x, float y, __half2& hi, __half2& lo) {
    hi = __float22half2_rn(make_float2(x, y));
    float2 h = __half22float2(hi);
    lo = __float22half2_rn(make_float2(x - h.x, y - h.y));
}

__device__ __forceinline__ uint32_t h2u(__half2 v) { return *(uint32_t*)&v; }

// ---------------------------------------------------------------------------
// Split-fp16 tensor GEMM with bias (unchanged from R4 — passing, 467us QKV)
// ---------------------------------------------------------------------------
#define APITCH 40
#define A_TILE_H (128 * APITCH)
#define STAGE_H  (4 * A_TILE_H)
#define GEMM_SMEM_BYTES (2 * STAGE_H * 2)

__global__ void __launch_bounds__(256, 2) gemm_split16_kernel(
    const float* __restrict__ A, const float* __restrict__ W,
    const float* __restrict__ bias, float* __restrict__ Out,
    int M, int K, int N)
{
    extern __shared__ __half smh[];

    const int tid  = threadIdx.x;
    const int w    = tid >> 5;
    const int lane = tid & 31;
    const int g    = lane >> 2;
    const int tig  = lane & 3;
    const int wm   = (w & 3) * 32;
    const int wn   = (w >> 2) * 64;

    const int bm = blockIdx.y * 128;
    const int bn = blockIdx.x * 128;

    const int am  = tid >> 3;
    const int akq = tid & 7;
    const int bn0 = tid & 31;
    const int bkq = tid >> 5;

    float acc[2][8][4] = {};
    float4 areg[4];
    float  breg[4][4];

    const int nchunk = K >> 5;

    #pragma unroll
    for (int l = 0; l < 4; l++) {
        areg[l] = *(const float4*)(A + (size_t)(bm + am + 32 * l) * K + (akq << 2));
        const float* wp = W + (size_t)(bkq << 2) * N + bn + bn0 + 32 * l;
        breg[l][0] = wp[0];
        breg[l][1] = wp[N];
        breg[l][2] = wp[2 * (size_t)N];
        breg[l][3] = wp[3 * (size_t)N];
    }
    {
        __half* Ahi = smh;
        __half* Alo = smh + A_TILE_H;
        __half* Bhi = smh + 2 * A_TILE_H;
        __half* Blo = smh + 3 * A_TILE_H;
        #pragma unroll
        for (int l = 0; l < 4; l++) {
            int m = am + 32 * l;
            __half2 h01, l01, h23, l23;
            split2(areg[l].x, areg[l].y, h01, l01);
            split2(areg[l].z, areg[l].w, h23, l23);
            *(__half2*)&Ahi[m * APITCH + (akq << 2)]     = h01;
            *(__half2*)&Ahi[m * APITCH + (akq << 2) + 2] = h23;
            *(__half2*)&Alo[m * APITCH + (akq << 2)]     = l01;
            *(__half2*)&Alo[m * APITCH + (akq << 2) + 2] = l23;
            int n = bn0 + 32 * l;
            split2(breg[l][0], breg[l][1], h01, l01);
            split2(breg[l][2], breg[l][3], h23, l23);
            *(__half2*)&Bhi[n * APITCH + (bkq << 2)]     = h01;
            *(__half2*)&Bhi[n * APITCH + (bkq << 2) + 2] = h23;
            *(__half2*)&Blo[n * APITCH + (bkq << 2)]     = l01;
            *(__half2*)&Blo[n * APITCH + (bkq << 2) + 2] = l23;
        }
    }
    __syncthreads();

    for (int c = 0; c < nchunk; c++) {
        if (c + 1 < nchunk) {
            const int k0 = (c + 1) << 5;
            #pragma unroll
            for (int l = 0; l < 4; l++) {
                areg[l] = *(const float4*)(A + (size_t)(bm + am + 32 * l) * K + k0 + (akq << 2));
                const float* wp = W + (size_t)(k0 + (bkq << 2)) * N + bn + bn0 + 32 * l;
                breg[l][0] = wp[0];
                breg[l][1] = wp[N];
                breg[l][2] = wp[2 * (size_t)N];
                breg[l][3] = wp[3 * (size_t)N];
            }
        }

        const __half* Ahi = smh + (c & 1) * STAGE_H;
        const __half* Alo = Ahi + A_TILE_H;
        const __half* Bhi = Ahi + 2 * A_TILE_H;
        const __half* Blo = Ahi + 3 * A_TILE_H;

        #pragma unroll
        for (int ks = 0; ks < 2; ks++) {
            const int ck = (ks << 4) + (tig << 1);
            uint32_t ah[2][4], al[2][4];
            #pragma unroll
            for (int ti = 0; ti < 2; ti++) {
                const int r0 = wm + (ti << 4) + g;
                ah[ti][0] = *(const uint32_t*)&Ahi[r0 * APITCH + ck];
                ah[ti][1] = *(const uint32_t*)&Ahi[(r0 + 8) * APITCH + ck];
                ah[ti][2] = *(const uint32_t*)&Ahi[r0 * APITCH + ck + 8];
                ah[ti][3] = *(const uint32_t*)&Ahi[(r0 + 8) * APITCH + ck + 8];
                al[ti][0] = *(const uint32_t*)&Alo[r0 * APITCH + ck];
                al[ti][1] = *(const uint32_t*)&Alo[(r0 + 8) * APITCH + ck];
                al[ti][2] = *(const uint32_t*)&Alo[r0 * APITCH + ck + 8];
                al[ti][3] = *(const uint32_t*)&Alo[(r0 + 8) * APITCH + ck + 8];
            }
            #pragma unroll
            for (int j = 0; j < 8; j++) {
                const int col = wn + (j << 3) + g;
                uint32_t bh[2], bl[2];
                bh[0] = *(const uint32_t*)&Bhi[col * APITCH + ck];
                bh[1] = *(const uint32_t*)&Bhi[col * APITCH + ck + 8];
                bl[0] = *(const uint32_t*)&Blo[col * APITCH + ck];
                bl[1] = *(const uint32_t*)&Blo[col * APITCH + ck + 8];
                #pragma unroll
                for (int ti = 0; ti < 2; ti++) {
                    mma_f16(acc[ti][j], ah[ti], bh);
                    mma_f16(acc[ti][j], ah[ti], bl);
                    mma_f16(acc[ti][j], al[ti], bh);
                }
            }
        }

        if (c + 1 < nchunk) {
            __half* Ahin = smh + ((c + 1) & 1) * STAGE_H;
            __half* Alon = Ahin + A_TILE_H;
            __half* Bhin = Ahin + 2 * A_TILE_H;
            __half* Blon = Ahin + 3 * A_TILE_H;
            #pragma unroll
            for (int l = 0; l < 4; l++) {
                int m = am + 32 * l;
                __half2 h01, l01, h23, l23;
                split2(areg[l].x, areg[l].y, h01, l01);
                split2(areg[l].z, areg[l].w, h23, l23);
                *(__half2*)&Ahin[m * APITCH + (akq << 2)]     = h01;
                *(__half2*)&Ahin[m * APITCH + (akq << 2) + 2] = h23;
                *(__half2*)&Alon[m * APITCH + (akq << 2)]     = l01;
                *(__half2*)&Alon[m * APITCH + (akq << 2) + 2] = l23;
                int n = bn0 + 32 * l;
                split2(breg[l][0], breg[l][1], h01, l01);
                split2(breg[l][2], breg[l][3], h23, l23);
                *(__half2*)&Bhin[n * APITCH + (bkq << 2)]     = h01;
                *(__half2*)&Bhin[n * APITCH + (bkq << 2) + 2] = h23;
                *(__half2*)&Blon[n * APITCH + (bkq << 2)]     = l01;
                *(__half2*)&Blon[n * APITCH + (bkq << 2) + 2] = l23;
            }
        }
        __syncthreads();
    }

    #pragma unroll
    for (int j = 0; j < 8; j++) {
        const int col = bn + wn + (j << 3) + (tig << 1);
        const float2 bb = *(const float2*)(bias + col);
        #pragma unroll
        for (int ti = 0; ti < 2; ti++) {
            const int row = bm + wm + (ti << 4) + g;
            float2 o0, o1;
            o0.x = acc[ti][j][0] + bb.x;
            o0.y = acc[ti][j][1] + bb.y;
            o1.x = acc[ti][j][2] + bb.x;
            o1.y = acc[ti][j][3] + bb.y;
            *(float2*)(Out + (size_t)row * N + col)       = o0;
            *(float2*)(Out + (size_t)(row + 8) * N + col) = o1;
        }
    }
}

// ---------------------------------------------------------------------------
// Split-fp16 tensor-core causal flash attention.
// Grid (T/128, H, B), 256 threads = 8 warps; warp w owns Q rows 16w..16w+15.
// K tiles of 64 kv. S and O in register fragments (m16n8k16 layout).
// K smem [kv][d] pitch 72 halves; V smem transposed [d][kv] pitch 72.
// 3-term split MMA for both S=QK^T and O+=PV.
// ---------------------------------------------------------------------------
#define KPITCH 72
#define ATTN_TC_SMEM (128 * KPITCH * 2 * 2)   // 36864 bytes (Q phase == K/V phase)

__global__ void __launch_bounds__(256) attn_tc_kernel(
    const float* __restrict__ qkv, float* __restrict__ y)
{
    extern __shared__ __half sha[];

    const int tid  = threadIdx.x;
    const int w    = tid >> 5;
    const int lane = tid & 31;
    const int g    = lane >> 2;
    const int tig  = lane & 3;
    const int qi   = blockIdx.x;
    const int h    = blockIdx.y;
    const int b    = blockIdx.z;
    const int qblock = qi * 128;

    const float* qbase = qkv + (size_t)b * T_ * W3_ + h * D_;
    const float* kbase = qbase + C_;
    const float* vbase = qbase + 2 * C_;

    // ---- Phase 0: stage Q (hi/lo) and extract per-warp A fragments ----
    {
        __half* Qhi = sha;
        __half* Qlo = sha + 128 * KPITCH;
        #pragma unroll
        for (int l = 0; l < 8; l++) {
            int idx = tid + 256 * l;
            int r   = idx >> 4;
            int d4  = (idx & 15) << 2;
            float4 v = *(const float4*)(qbase + (size_t)(qblock + r) * W3_ + d4);
            __half2 h01, l01, h23, l23;
            split2(v.x, v.y, h01, l01);
            split2(v.z, v.w, h23, l23);
            *(__half2*)&Qhi[r * KPITCH + d4]     = h01;
            *(__half2*)&Qhi[r * KPITCH + d4 + 2] = h23;
            *(__half2*)&Qlo[r * KPITCH + d4]     = l01;
            *(__half2*)&Qlo[r * KPITCH + d4 + 2] = l23;
        }
    }
    __syncthreads();

    uint32_t qh[4][4], ql[4][4];
    {
        const __half* Qhi = sha;
        const __half* Qlo = sha + 128 * KPITCH;
        const int r0 = (w << 4) + g;
        #pragma unroll
        for (int kc = 0; kc < 4; kc++) {
            const int ck = (kc << 4) + (tig << 1);
            qh[kc][0] = *(const uint32_t*)&Qhi[r0 * KPITCH + ck];
            qh[kc][1] = *(const uint32_t*)&Qhi[(r0 + 8) * KPITCH + ck];
            qh[kc][2] = *(const uint32_t*)&Qhi[r0 * KPITCH + ck + 8];
            qh[kc][3] = *(const uint32_t*)&Qhi[(r0 + 8) * KPITCH + ck + 8];
            ql[kc][0] = *(const uint32_t*)&Qlo[r0 * KPITCH + ck];
            ql[kc][1] = *(const uint32_t*)&Qlo[(r0 + 8) * KPITCH + ck];
            ql[kc][2] = *(const uint32_t*)&Qlo[r0 * KPITCH + ck + 8];
            ql[kc][3] = *(const uint32_t*)&Qlo[(r0 + 8) * KPITCH + ck + 8];
        }
    }

    __half* Khi = sha;
    __half* Klo = sha + 64 * KPITCH;
    __half* Vhi = sha + 2 * 64 * KPITCH;
    __half* Vlo = sha + 3 * 64 * KPITCH;

    const int row0 = qblock + (w << 4) + g;   // global q row of c0/c1
    const int row1 = row0 + 8;                // global q row of c2/c3

    float m0 = -1e30f, m1 = -1e30f, l0 = 0.0f, l1 = 0.0f;
    float o[8][4] = {};

    const int nkj = 2 * qi + 2;

    for (int kj = 0; kj < nkj; kj++) {
        __syncthreads();   // prior reads of smem done (incl. Q fragments)

        // ---- stage K [kv][d] and V transposed [d][kv], hi/lo ----
        #pragma unroll
        for (int l = 0; l < 4; l++) {
            int idx = tid + 256 * l;
            int r   = idx >> 4;            // kv 0..63
            int d4  = (idx & 15) << 2;
            const size_t rowoff = (size_t)(kj * 64 + r) * W3_ + d4;
            float4 kv4 = *(const float4*)(kbase + rowoff);
            __half2 h01, l01, h23, l23;
            split2(kv4.x, kv4.y, h01, l01);
            split2(kv4.z, kv4.w, h23, l23);
            *(__half2*)&Khi[r * KPITCH + d4]     = h01;
            *(__half2*)&Khi[r * KPITCH + d4 + 2] = h23;
            *(__half2*)&Klo[r * KPITCH + d4]     = l01;
            *(__half2*)&Klo[r * KPITCH + d4 + 2] = l23;

            float4 vv = *(const float4*)(vbase + rowoff);
            float vs[4] = {vv.x, vv.y, vv.z, vv.w};
            #pragma unroll
            for (int j = 0; j < 4; j++) {
                __half vh = __float2half_rn(vs[j]);
                __half vl = __float2half_rn(vs[j] - __half2float(vh));
                Vhi[(d4 + j) * KPITCH + r] = vh;
                Vlo[(d4 + j) * KPITCH + r] = vl;
            }
        }
        __syncthreads();

        // ---- S = Q @ K^T (3-term split) ----
        float sacc[8][4] = {};
        #pragma unroll
        for (int kc = 0; kc < 4; kc++) {
            const int ck = (kc << 4) + (tig << 1);
            #pragma unroll
            for (int jn = 0; jn < 8; jn++) {
                const int kr = ((jn << 3) + g) * KPITCH + ck;
                uint32_t bh[2], bl[2];
                bh[0] = *(const uint32_t*)&Khi[kr];
                bh[1] = *(const uint32_t*)&Khi[kr + 8];
                bl[0] = *(const uint32_t*)&Klo[kr];
                bl[1] = *(const uint32_t*)&Klo[kr + 8];
                mma_f16(sacc[jn], qh[kc], bh);
                mma_f16(sacc[jn], qh[kc], bl);
                mma_f16(sacc[jn], ql[kc], bh);
            }
        }

        // ---- mask + scale(*8) + online softmax ----
        float tm0 = -1e30f, tm1 = -1e30f;
        #pragma unroll
        for (int jn = 0; jn < 8; jn++) {
            const int c0 = kj * 64 + (jn << 3) + (tig << 1);
            float v0 = (c0     <= row0) ? sacc[jn][0] * 8.0f : -1e30f;
            float v1 = (c0 + 1 <= row0) ? sacc[jn][1] * 8.0f : -1e30f;
            float v2 = (c0     <= row1) ? sacc[jn][2] * 8.0f : -1e30f;
            float v3 = (c0 + 1 <= row1) ? sacc[jn][3] * 8.0f : -1e30f;
            sacc[jn][0] = v0; sacc[jn][1] = v1;
            sacc[jn][2] = v2; sacc[jn][3] = v3;
            tm0 = fmaxf(tm0, fmaxf(v0, v1));
            tm1 = fmaxf(tm1, fmaxf(v2, v3));
        }
        tm0 = fmaxf(tm0, __shfl_xor_sync(0xffffffffu, tm0, 1));
        tm0 = fmaxf(tm0, __shfl_xor_sync(0xffffffffu, tm0, 2));
        tm1 = fmaxf(tm1, __shfl_xor_sync(0xffffffffu, tm1, 1));
        tm1 = fmaxf(tm1, __shfl_xor_sync(0xffffffffu, tm1, 2));

        const float mn0 = fmaxf(m0, tm0);
        const float mn1 = fmaxf(m1, tm1);
        const float al0 = __expf(m0 - mn0);
        const float al1 = __expf(m1 - mn1);
        m0 = mn0; m1 = mn1;

        float s0 = 0.0f, s1 = 0.0f;
        #pragma unroll
        for (int jn = 0; jn < 8; jn++) {
            float p0 = __expf(sacc[jn][0] - mn0);
            float p1 = __expf(sacc[jn][1] - mn0);
            float p2 = __expf(sacc[jn][2] - mn1);
            float p3 = __expf(sacc[jn][3] - mn1);
            sacc[jn][0] = p0; sacc[jn][1] = p1;
            sacc[jn][2] = p2; sacc[jn][3] = p3;
            s0 += p0 + p1;
            s1 += p2 + p3;
        }
        s0 += __shfl_xor_sync(0xffffffffu, s0, 1);
        s0 += __shfl_xor_sync(0xffffffffu, s0, 2);
        s1 += __shfl_xor_sync(0xffffffffu, s1, 1);
        s1 += __shfl_xor_sync(0xffffffffu, s1, 2);
        l0 = l0 * al0 + s0;
        l1 = l1 * al1 + s1;

        // ---- rescale O, then O += P @ V (3-term split) ----
        #pragma unroll
        for (int jd = 0; jd < 8; jd++) {
            o[jd][0] *= al0; o[jd][1] *= al0;
            o[jd][2] *= al1; o[jd][3] *= al1;
        }

        #pragma unroll
        for (int kc = 0; kc < 4; kc++) {
            uint32_t ph[4], pl[4];
            {
                __half2 hh, ll;
                split2(sacc[2 * kc][0], sacc[2 * kc][1], hh, ll);
                ph[0] = h2u(hh); pl[0] = h2u(ll);
                split2(sacc[2 * kc][2], sacc[2 * kc][3], hh, ll);
                ph[1] = h2u(hh); pl[1] = h2u(ll);
                split2(sacc[2 * kc + 1][0], sacc[2 * kc + 1][1], hh, ll);
                ph[2] = h2u(hh); pl[2] = h2u(ll);
                split2(sacc[2 * kc + 1][2], sacc[2 * kc + 1][3], hh, ll);
                ph[3] = h2u(hh); pl[3] = h2u(ll);
            }
            const int ck = (kc << 4) + (tig << 1);
            #pragma unroll
            for (int jd = 0; jd < 8; jd++) {
                const int vr = ((jd << 3) + g) * KPITCH + ck;
                uint32_t bh[2], bl[2];
                bh[0] = *(const uint32_t*)&Vhi[vr];
                bh[1] = *(const uint32_t*)&Vhi[vr + 8];
                bl[0] = *(const uint32_t*)&Vlo[vr];
                bl[1] = *(const uint32_t*)&Vlo[vr + 8];
                mma_f16(o[jd], ph, bh);
                mma_f16(o[jd], ph, bl);
                mma_f16(o[jd], pl, bh);
            }
        }
    }

    // ---- epilogue: normalize, write y [b, t, h*64 + d] ----
    const float inv0 = 1.0f / l0;
    const float inv1 = 1.0f / l1;
    float* yr0 = y + (size_t)(b * T_ + row0) * C_ + h * D_ + (tig << 1);
    float* yr1 = yr0 + 8 * C_;
    #pragma unroll
    for (int jd = 0; jd < 8; jd++) {
        float2 a, c;
        a.x = o[jd][0] * inv0; a.y = o[jd][1] * inv0;
        c.x = o[jd][2] * inv1; c.y = o[jd][3] * inv1;
        *(float2*)(yr0 + (jd << 3)) = a;
        *(float2*)(yr1 + (jd << 3)) = c;
    }
}

// ---------------------------------------------------------------------------
// Launch
// ---------------------------------------------------------------------------
extern "C" void kernel_launch(void* const* d_in, const int* in_sizes, int n_in,
                              void* d_out, int out_size)
{
    const float* x      = (const float*)d_in[0];
    const float* w_attn = (const float*)d_in[1];
    const float* b_attn = (const float*)d_in[2];
    const float* w_proj = (const float*)d_in[3];
    const float* b_proj = (const float*)d_in[4];
    float* out = (float*)d_out;

    float* qkv = nullptr;
    float* y   = nullptr;
    cudaGetSymbolAddress((void**)&qkv, g_qkv);
    cudaGetSymbolAddress((void**)&y, g_y);

    cudaFuncSetAttribute(gemm_split16_kernel,
                         cudaFuncAttributeMaxDynamicSharedMemorySize,
                         GEMM_SMEM_BYTES);

    // qkv = x @ w_attn + b_attn : [8192,1024]@[1024,3072]
    gemm_split16_kernel<<<dim3(W3_ / 128, M_ / 128), 256, GEMM_SMEM_BYTES>>>(
        x, w_attn, b_attn, qkv, M_, C_, W3_);

    // y = causal_attention(q, k, v) — split-fp16 tensor cores
    attn_tc_kernel<<<dim3(T_ / 128, H_, B_), 256, ATTN_TC_SMEM>>>(qkv, y);

    // out = y @ w_proj + b_proj : [8192,1024]@[1024,1024]
    gemm_split16_kernel<<<dim3(C_ / 128, M_ / 128), 256, GEMM_SMEM_BYTES>>>(
        y, w_proj, b_proj, out, M_, C_, C_);
}

// round 6
// speedup vs baseline: 2.9213x; 1.2580x over previous
#include <cuda_runtime.h>
#include <cuda_fp16.h>
#include <cstdint>

// Problem constants
#define B_  4
#define T_  2048
#define C_  1024
#define H_  16
#define D_  64
#define M_  (B_ * T_)      // 8192 rows
#define W3_ (3 * C_)       // 3072

// Scratch (allocation-free rule: __device__ globals)
__device__ float g_qkv[(size_t)M_ * W3_];  // [8192, 3072] fp32
__device__ float g_y[(size_t)M_ * C_];     // [8192, 1024] fp32

// ---------------------------------------------------------------------------
// helpers
// ---------------------------------------------------------------------------
__device__ __forceinline__ void mma_f16(float* acc, const uint32_t* a,
                                        const uint32_t* b) {
    asm volatile(
        "mma.sync.aligned.m16n8k16.row.col.f32.f16.f16.f32 "
        "{%0,%1,%2,%3}, {%4,%5,%6,%7}, {%8,%9}, {%0,%1,%2,%3};"
        : "+f"(acc[0]), "+f"(acc[1]), "+f"(acc[2]), "+f"(acc[3])
        : "r"(a[0]), "r"(a[1]), "r"(a[2]), "r"(a[3]),
          "r"(b[0]), "r"(b[1]));
}

__device__ __forceinline__ void split2(float x, float y, __half2& hi, __half2& lo) {
    hi = __float22half2_rn(make_float2(x, y));
    float2 h = __half22float2(hi);
    lo = __float22half2_rn(make_float2(x - h.x, y - h.y));
}

__device__ __forceinline__ uint32_t h2u(__half2 v) { return *(uint32_t*)&v; }

__device__ __forceinline__ uint32_t smem_u32(const void* p) {
    uint32_t a;
    asm("{ .reg .u64 t; cvta.to.shared.u64 t, %1; cvt.u32.u64 %0, t; }"
        : "=r"(a) : "l"(p));
    return a;
}

__device__ __forceinline__ void ldsm_x4(uint32_t* r, uint32_t addr) {
    asm volatile("ldmatrix.sync.aligned.m8n8.x4.shared.b16 {%0,%1,%2,%3}, [%4];"
                 : "=r"(r[0]), "=r"(r[1]), "=r"(r[2]), "=r"(r[3]) : "r"(addr));
}
__device__ __forceinline__ void ldsm_x4_t(uint32_t* r, uint32_t addr) {
    asm volatile("ldmatrix.sync.aligned.m8n8.x4.trans.shared.b16 {%0,%1,%2,%3}, [%4];"
                 : "=r"(r[0]), "=r"(r[1]), "=r"(r[2]), "=r"(r[3]) : "r"(addr));
}

// ---------------------------------------------------------------------------
// Split-fp16 tensor GEMM with bias: Out[M,N] = A[M,K] @ W[K,N] + bias[N]
// 128x128 CTA tile, BK=32, 8 warps (4Mx2N), ldmatrix fragment loads.
// ---------------------------------------------------------------------------
#define APITCH 40
#define A_TILE_H (128 * APITCH)          // halves per operand tile
#define STAGE_H  (4 * A_TILE_H)
#define GEMM_SMEM_BYTES (2 * STAGE_H * 2)
#define GA_LO_B  (2 * A_TILE_H)          // byte offsets within a stage
#define GB_HI_B  (4 * A_TILE_H)
#define GB_LO_B  (6 * A_TILE_H)

__global__ void __launch_bounds__(256, 2) gemm_split16_kernel(
    const float* __restrict__ A, const float* __restrict__ W,
    const float* __restrict__ bias, float* __restrict__ Out,
    int M, int K, int N)
{
    extern __shared__ __half smh[];

    const int tid  = threadIdx.x;
    const int w    = tid >> 5;
    const int lane = tid & 31;
    const int g    = lane >> 2;
    const int tig  = lane & 3;
    const int wm   = (w & 3) * 32;
    const int wn   = (w >> 2) * 64;

    const int lrow16 = lane & 15;          // ldmatrix row within 16
    const int lhi8   = (lane & 16) >> 1;   // 0 or 8 (column select / row select)
    const int l8     = lane & 8;

    const int bm = blockIdx.y * 128;
    const int bn = blockIdx.x * 128;

    const int am  = tid >> 3;
    const int akq = tid & 7;
    const int bn0 = tid & 31;
    const int bkq = tid >> 5;

    const uint32_t sbase = smem_u32(smh);

    float acc[2][8][4] = {};
    float4 areg[4];
    float  breg[4][4];

    const int nchunk = K >> 5;

    // ---- prologue: global load + stage chunk 0 ----
    #pragma unroll
    for (int l = 0; l < 4; l++) {
        areg[l] = *(const float4*)(A + (size_t)(bm + am + 32 * l) * K + (akq << 2));
        const float* wp = W + (size_t)(bkq << 2) * N + bn + bn0 + 32 * l;
        breg[l][0] = wp[0];
        breg[l][1] = wp[N];
        breg[l][2] = wp[2 * (size_t)N];
        breg[l][3] = wp[3 * (size_t)N];
    }
    {
        __half* Ahi = smh;
        __half* Alo = smh + A_TILE_H;
        __half* Bhi = smh + 2 * A_TILE_H;
        __half* Blo = smh + 3 * A_TILE_H;
        #pragma unroll
        for (int l = 0; l < 4; l++) {
            int m = am + 32 * l;
            __half2 h01, l01, h23, l23;
            split2(areg[l].x, areg[l].y, h01, l01);
            split2(areg[l].z, areg[l].w, h23, l23);
            *(__half2*)&Ahi[m * APITCH + (akq << 2)]     = h01;
            *(__half2*)&Ahi[m * APITCH + (akq << 2) + 2] = h23;
            *(__half2*)&Alo[m * APITCH + (akq << 2)]     = l01;
            *(__half2*)&Alo[m * APITCH + (akq << 2) + 2] = l23;
            int n = bn0 + 32 * l;
            split2(breg[l][0], breg[l][1], h01, l01);
            split2(breg[l][2], breg[l][3], h23, l23);
            *(__half2*)&Bhi[n * APITCH + (bkq << 2)]     = h01;
            *(__half2*)&Bhi[n * APITCH + (bkq << 2) + 2] = h23;
            *(__half2*)&Blo[n * APITCH + (bkq << 2)]     = l01;
            *(__half2*)&Blo[n * APITCH + (bkq << 2) + 2] = l23;
        }
    }
    __syncthreads();

    for (int c = 0; c < nchunk; c++) {
        if (c + 1 < nchunk) {
            const int k0 = (c + 1) << 5;
            #pragma unroll
            for (int l = 0; l < 4; l++) {
                areg[l] = *(const float4*)(A + (size_t)(bm + am + 32 * l) * K + k0 + (akq << 2));
                const float* wp = W + (size_t)(k0 + (bkq << 2)) * N + bn + bn0 + 32 * l;
                breg[l][0] = wp[0];
                breg[l][1] = wp[N];
                breg[l][2] = wp[2 * (size_t)N];
                breg[l][3] = wp[3 * (size_t)N];
            }
        }

        const uint32_t sA = sbase + ((c & 1) ? STAGE_H * 2 : 0);

        #pragma unroll
        for (int ks = 0; ks < 2; ks++) {
            uint32_t ah[2][4], al[2][4];
            #pragma unroll
            for (int ti = 0; ti < 2; ti++) {
                const uint32_t aoff =
                    2 * ((wm + (ti << 4) + lrow16) * APITCH + (ks << 4) + lhi8);
                ldsm_x4(ah[ti], sA + aoff);
                ldsm_x4(al[ti], sA + GA_LO_B + aoff);
            }
            #pragma unroll
            for (int jp = 0; jp < 4; jp++) {
                const uint32_t boff =
                    2 * ((wn + (jp << 4) + (lane & 7) + lhi8) * APITCH + (ks << 4) + l8);
                uint32_t bh[4], bl[4];
                ldsm_x4(bh, sA + GB_HI_B + boff);
                ldsm_x4(bl, sA + GB_LO_B + boff);
                #pragma unroll
                for (int ti = 0; ti < 2; ti++) {
                    mma_f16(acc[ti][2 * jp],     ah[ti], bh);
                    mma_f16(acc[ti][2 * jp],     ah[ti], bl);
                    mma_f16(acc[ti][2 * jp],     al[ti], bh);
                    mma_f16(acc[ti][2 * jp + 1], ah[ti], bh + 2);
                    mma_f16(acc[ti][2 * jp + 1], ah[ti], bl + 2);
                    mma_f16(acc[ti][2 * jp + 1], al[ti], bh + 2);
                }
            }
        }

        if (c + 1 < nchunk) {
            __half* Ahin = smh + ((c + 1) & 1) * STAGE_H;
            __half* Alon = Ahin + A_TILE_H;
            __half* Bhin = Ahin + 2 * A_TILE_H;
            __half* Blon = Ahin + 3 * A_TILE_H;
            #pragma unroll
            for (int l = 0; l < 4; l++) {
                int m = am + 32 * l;
                __half2 h01, l01, h23, l23;
                split2(areg[l].x, areg[l].y, h01, l01);
                split2(areg[l].z, areg[l].w, h23, l23);
                *(__half2*)&Ahin[m * APITCH + (akq << 2)]     = h01;
                *(__half2*)&Ahin[m * APITCH + (akq << 2) + 2] = h23;
                *(__half2*)&Alon[m * APITCH + (akq << 2)]     = l01;
                *(__half2*)&Alon[m * APITCH + (akq << 2) + 2] = l23;
                int n = bn0 + 32 * l;
                split2(breg[l][0], breg[l][1], h01, l01);
                split2(breg[l][2], breg[l][3], h23, l23);
                *(__half2*)&Bhin[n * APITCH + (bkq << 2)]     = h01;
                *(__half2*)&Bhin[n * APITCH + (bkq << 2) + 2] = h23;
                *(__half2*)&Blon[n * APITCH + (bkq << 2)]     = l01;
                *(__half2*)&Blon[n * APITCH + (bkq << 2) + 2] = l23;
            }
        }
        __syncthreads();
    }

    // ---- epilogue: bias + store ----
    #pragma unroll
    for (int j = 0; j < 8; j++) {
        const int col = bn + wn + (j << 3) + (tig << 1);
        const float2 bb = *(const float2*)(bias + col);
        #pragma unroll
        for (int ti = 0; ti < 2; ti++) {
            const int row = bm + wm + (ti << 4) + g;
            float2 o0, o1;
            o0.x = acc[ti][j][0] + bb.x;
            o0.y = acc[ti][j][1] + bb.y;
            o1.x = acc[ti][j][2] + bb.x;
            o1.y = acc[ti][j][3] + bb.y;
            *(float2*)(Out + (size_t)row * N + col)       = o0;
            *(float2*)(Out + (size_t)(row + 8) * N + col) = o1;
        }
    }
}

// ---------------------------------------------------------------------------
// Split-fp16 tensor-core causal flash attention (ldmatrix fragment loads).
// Grid (T/128, H, B), 256 threads = 8 warps; warp w owns Q rows 16w..16w+15.
// K and V stored NATURAL [kv][d] pitch 72; V fragments via ldmatrix.trans.
// ---------------------------------------------------------------------------
#define KPITCH 72
#define ATTN_TC_SMEM (128 * KPITCH * 2 * 2)   // 36864 bytes
#define AK_LO_B (64 * KPITCH * 2)             //  9216
#define AV_HI_B (2 * 64 * KPITCH * 2)         // 18432
#define AV_LO_B (3 * 64 * KPITCH * 2)         // 27648
#define AQ_LO_B (128 * KPITCH * 2)            // 18432 (phase 0)

__global__ void __launch_bounds__(256) attn_tc_kernel(
    const float* __restrict__ qkv, float* __restrict__ y)
{
    extern __shared__ __half sha[];

    const int tid  = threadIdx.x;
    const int w    = tid >> 5;
    const int lane = tid & 31;
    const int g    = lane >> 2;
    const int tig  = lane & 3;
    const int lrow16 = lane & 15;
    const int lhi8   = (lane & 16) >> 1;
    const int l8     = lane & 8;
    const int qi   = blockIdx.x;
    const int h    = blockIdx.y;
    const int b    = blockIdx.z;
    const int qblock = qi * 128;

    const uint32_t sbase = smem_u32(sha);

    const float* qbase = qkv + (size_t)b * T_ * W3_ + h * D_;
    const float* kbase = qbase + C_;
    const float* vbase = qbase + 2 * C_;

    // ---- Phase 0: stage Q (hi/lo) ----
    {
        __half* Qhi = sha;
        __half* Qlo = sha + 128 * KPITCH;
        #pragma unroll
        for (int l = 0; l < 8; l++) {
            int idx = tid + 256 * l;
            int r   = idx >> 4;
            int d4  = (idx & 15) << 2;
            float4 v = *(const float4*)(qbase + (size_t)(qblock + r) * W3_ + d4);
            __half2 h01, l01, h23, l23;
            split2(v.x, v.y, h01, l01);
            split2(v.z, v.w, h23, l23);
            *(__half2*)&Qhi[r * KPITCH + d4]     = h01;
            *(__half2*)&Qhi[r * KPITCH + d4 + 2] = h23;
            *(__half2*)&Qlo[r * KPITCH + d4]     = l01;
            *(__half2*)&Qlo[r * KPITCH + d4 + 2] = l23;
        }
    }
    __syncthreads();

    // Q fragments via ldmatrix (A pattern)
    uint32_t qh[4][4], ql[4][4];
    #pragma unroll
    for (int kc = 0; kc < 4; kc++) {
        const uint32_t qoff = 2 * (((w << 4) + lrow16) * KPITCH + (kc << 4) + lhi8);
        ldsm_x4(qh[kc], sbase + qoff);
        ldsm_x4(ql[kc], sbase + AQ_LO_B + qoff);
    }

    __half* Khi = sha;
    __half* Klo = sha + 64 * KPITCH;
    __half* Vhi = sha + 2 * 64 * KPITCH;
    __half* Vlo = sha + 3 * 64 * KPITCH;

    const int row0 = qblock + (w << 4) + g;
    const int row1 = row0 + 8;

    float m0 = -1e30f, m1 = -1e30f, l0 = 0.0f, l1 = 0.0f;
    float o[8][4] = {};

    const int nkj = 2 * qi + 2;

    for (int kj = 0; kj < nkj; kj++) {
        __syncthreads();

        // ---- stage K and V, both natural [kv][d], hi/lo ----
        #pragma unroll
        for (int l = 0; l < 4; l++) {
            int idx = tid + 256 * l;
            int r   = idx >> 4;
            int d4  = (idx & 15) << 2;
            const size_t rowoff = (size_t)(kj * 64 + r) * W3_ + d4;
            float4 kv4 = *(const float4*)(kbase + rowoff);
            __half2 h01, l01, h23, l23;
            split2(kv4.x, kv4.y, h01, l01);
            split2(kv4.z, kv4.w, h23, l23);
            *(__half2*)&Khi[r * KPITCH + d4]     = h01;
            *(__half2*)&Khi[r * KPITCH + d4 + 2] = h23;
            *(__half2*)&Klo[r * KPITCH + d4]     = l01;
            *(__half2*)&Klo[r * KPITCH + d4 + 2] = l23;

            float4 vv = *(const float4*)(vbase + rowoff);
            split2(vv.x, vv.y, h01, l01);
            split2(vv.z, vv.w, h23, l23);
            *(__half2*)&Vhi[r * KPITCH + d4]     = h01;
            *(__half2*)&Vhi[r * KPITCH + d4 + 2] = h23;
            *(__half2*)&Vlo[r * KPITCH + d4]     = l01;
            *(__half2*)&Vlo[r * KPITCH + d4 + 2] = l23;
        }
        __syncthreads();

        // ---- S = Q @ K^T (3-term split), K frags via ldmatrix (B pattern) ----
        float sacc[8][4] = {};
        #pragma unroll
        for (int kc = 0; kc < 4; kc++) {
            #pragma unroll
            for (int jnp = 0; jnp < 4; jnp++) {
                const uint32_t koff =
                    2 * (((jnp << 4) + (lane & 7) + lhi8) * KPITCH + (kc << 4) + l8);
                uint32_t kh[4], kl[4];
                ldsm_x4(kh, sbase + koff);
                ldsm_x4(kl, sbase + AK_LO_B + koff);
                mma_f16(sacc[2 * jnp],     qh[kc], kh);
                mma_f16(sacc[2 * jnp],     qh[kc], kl);
                mma_f16(sacc[2 * jnp],     ql[kc], kh);
                mma_f16(sacc[2 * jnp + 1], qh[kc], kh + 2);
                mma_f16(sacc[2 * jnp + 1], qh[kc], kl + 2);
                mma_f16(sacc[2 * jnp + 1], ql[kc], kh + 2);
            }
        }

        // ---- mask + scale(*8) + online softmax ----
        float tm0 = -1e30f, tm1 = -1e30f;
        #pragma unroll
        for (int jn = 0; jn < 8; jn++) {
            const int c0 = kj * 64 + (jn << 3) + (tig << 1);
            float v0 = (c0     <= row0) ? sacc[jn][0] * 8.0f : -1e30f;
            float v1 = (c0 + 1 <= row0) ? sacc[jn][1] * 8.0f : -1e30f;
            float v2 = (c0     <= row1) ? sacc[jn][2] * 8.0f : -1e30f;
            float v3 = (c0 + 1 <= row1) ? sacc[jn][3] * 8.0f : -1e30f;
            sacc[jn][0] = v0; sacc[jn][1] = v1;
            sacc[jn][2] = v2; sacc[jn][3] = v3;
            tm0 = fmaxf(tm0, fmaxf(v0, v1));
            tm1 = fmaxf(tm1, fmaxf(v2, v3));
        }
        tm0 = fmaxf(tm0, __shfl_xor_sync(0xffffffffu, tm0, 1));
        tm0 = fmaxf(tm0, __shfl_xor_sync(0xffffffffu, tm0, 2));
        tm1 = fmaxf(tm1, __shfl_xor_sync(0xffffffffu, tm1, 1));
        tm1 = fmaxf(tm1, __shfl_xor_sync(0xffffffffu, tm1, 2));

        const float mn0 = fmaxf(m0, tm0);
        const float mn1 = fmaxf(m1, tm1);
        const float al0 = __expf(m0 - mn0);
        const float al1 = __expf(m1 - mn1);
        m0 = mn0; m1 = mn1;

        float s0 = 0.0f, s1 = 0.0f;
        #pragma unroll
        for (int jn = 0; jn < 8; jn++) {
            float p0 = __expf(sacc[jn][0] - mn0);
            float p1 = __expf(sacc[jn][1] - mn0);
            float p2 = __expf(sacc[jn][2] - mn1);
            float p3 = __expf(sacc[jn][3] - mn1);
            sacc[jn][0] = p0; sacc[jn][1] = p1;
            sacc[jn][2] = p2; sacc[jn][3] = p3;
            s0 += p0 + p1;
            s1 += p2 + p3;
        }
        s0 += __shfl_xor_sync(0xffffffffu, s0, 1);
        s0 += __shfl_xor_sync(0xffffffffu, s0, 2);
        s1 += __shfl_xor_sync(0xffffffffu, s1, 1);
        s1 += __shfl_xor_sync(0xffffffffu, s1, 2);
        l0 = l0 * al0 + s0;
        l1 = l1 * al1 + s1;

        // ---- rescale O, then O += P @ V; V frags via ldmatrix.trans ----
        #pragma unroll
        for (int jd = 0; jd < 8; jd++) {
            o[jd][0] *= al0; o[jd][1] *= al0;
            o[jd][2] *= al1; o[jd][3] *= al1;
        }

        #pragma unroll
        for (int kc = 0; kc < 4; kc++) {
            uint32_t ph[4], pl[4];
            {
                __half2 hh, ll;
                split2(sacc[2 * kc][0], sacc[2 * kc][1], hh, ll);
                ph[0] = h2u(hh); pl[0] = h2u(ll);
                split2(sacc[2 * kc][2], sacc[2 * kc][3], hh, ll);
                ph[1] = h2u(hh); pl[1] = h2u(ll);
                split2(sacc[2 * kc + 1][0], sacc[2 * kc + 1][1], hh, ll);
                ph[2] = h2u(hh); pl[2] = h2u(ll);
                split2(sacc[2 * kc + 1][2], sacc[2 * kc + 1][3], hh, ll);
                ph[3] = h2u(hh); pl[3] = h2u(ll);
            }
            #pragma unroll
            for (int jdp = 0; jdp < 4; jdp++) {
                const uint32_t voff =
                    2 * (((kc << 4) + lrow16) * KPITCH + (jdp << 4) + lhi8);
                uint32_t vh[4], vl[4];
                ldsm_x4_t(vh, sbase + AV_HI_B + voff);
                ldsm_x4_t(vl, sbase + AV_LO_B + voff);
                mma_f16(o[2 * jdp],     ph, vh);
                mma_f16(o[2 * jdp],     ph, vl);
                mma_f16(o[2 * jdp],     pl, vh);
                mma_f16(o[2 * jdp + 1], ph, vh + 2);
                mma_f16(o[2 * jdp + 1], ph, vl + 2);
                mma_f16(o[2 * jdp + 1], pl, vh + 2);
            }
        }
    }

    // ---- epilogue: normalize, write y ----
    const float inv0 = 1.0f / l0;
    const float inv1 = 1.0f / l1;
    float* yr0 = y + (size_t)(b * T_ + row0) * C_ + h * D_ + (tig << 1);
    float* yr1 = yr0 + 8 * C_;
    #pragma unroll
    for (int jd = 0; jd < 8; jd++) {
        float2 a, c;
        a.x = o[jd][0] * inv0; a.y = o[jd][1] * inv0;
        c.x = o[jd][2] * inv1; c.y = o[jd][3] * inv1;
        *(float2*)(yr0 + (jd << 3)) = a;
        *(float2*)(yr1 + (jd << 3)) = c;
    }
}

// ---------------------------------------------------------------------------
// Launch
// ---------------------------------------------------------------------------
extern "C" void kernel_launch(void* const* d_in, const int* in_sizes, int n_in,
                              void* d_out, int out_size)
{
    const float* x      = (const float*)d_in[0];
    const float* w_attn = (const float*)d_in[1];
    const float* b_attn = (const float*)d_in[2];
    const float* w_proj = (const float*)d_in[3];
    const float* b_proj = (const float*)d_in[4];
    float* out = (float*)d_out;

    float* qkv = nullptr;
    float* y   = nullptr;
    cudaGetSymbolAddress((void**)&qkv, g_qkv);
    cudaGetSymbolAddress((void**)&y, g_y);

    cudaFuncSetAttribute(gemm_split16_kernel,
                         cudaFuncAttributeMaxDynamicSharedMemorySize,
                         GEMM_SMEM_BYTES);

    // qkv = x @ w_attn + b_attn : [8192,1024]@[1024,3072]
    gemm_split16_kernel<<<dim3(W3_ / 128, M_ / 128), 256, GEMM_SMEM_BYTES>>>(
        x, w_attn, b_attn, qkv, M_, C_, W3_);

    // y = causal_attention(q, k, v) — split-fp16 tensor cores
    attn_tc_kernel<<<dim3(T_ / 128, H_, B_), 256, ATTN_TC_SMEM>>>(qkv, y);

    // out = y @ w_proj + b_proj : [8192,1024]@[1024,1024]
    gemm_split16_kernel<<<dim3(C_ / 128, M_ / 128), 256, GEMM_SMEM_BYTES>>>(
        y, w_proj, b_proj, out, M_, C_, C_);
}